// round 1
// baseline (speedup 1.0000x reference)
#include <cuda_runtime.h>
#include <cuda_bf16.h>
#include <mma.h>
#include <math.h>

using namespace nvcuda;

// Problem dims (fixed by the reference)
#define DMODEL 1024
#define DFF    4096
#define NHEADS 16
#define HEADD  64
#define SEQ    2048
#define NBATCH 2
#define NTOK   (NBATCH * SEQ)   // 4096

// ---------------- scratch (static device globals; allocation-free at launch) ----
__device__ float g_h  [(size_t)NTOK * DMODEL];           // 16 MB  LN1 output
__device__ float g_q  [(size_t)NTOK * DMODEL];           // 16 MB
__device__ float g_k  [(size_t)NTOK * DMODEL];           // 16 MB
__device__ float g_v  [(size_t)NTOK * DMODEL];           // 16 MB
__device__ float g_sc [(size_t)NBATCH * NHEADS * SEQ * SEQ]; // 512 MB attention scores
__device__ float g_att[(size_t)NTOK * DMODEL];           // 16 MB
__device__ float g_x1 [(size_t)NTOK * DMODEL];           // 16 MB
__device__ float g_h2 [(size_t)NTOK * DMODEL];           // 16 MB
__device__ float g_ff [(size_t)NTOK * DFF];              // 64 MB

// ---------------- helpers ----------------
__device__ __forceinline__ float warpSum(float v) {
    #pragma unroll
    for (int o = 16; o > 0; o >>= 1) v += __shfl_xor_sync(0xffffffffu, v, o);
    return v;
}
__device__ __forceinline__ float warpMax(float v) {
    #pragma unroll
    for (int o = 16; o > 0; o >>= 1) v = fmaxf(v, __shfl_xor_sync(0xffffffffu, v, o));
    return v;
}
__device__ __forceinline__ float gelu_f(float x) {
    const float c = 0.7978845608028654f; // sqrt(2/pi)
    float x3 = x * x * x;
    return 0.5f * x * (1.0f + tanhf(c * (x + 0.044715f * x3)));
}

// ---------------- LayerNorm: one block per row of 1024 ----------------
__global__ void __launch_bounds__(256) ln_kernel(
    const float* __restrict__ X, const float* __restrict__ g,
    const float* __restrict__ b, float* __restrict__ Y)
{
    long row = blockIdx.x;
    const float* x = X + row * DMODEL;
    float v[4];
    float s = 0.f, s2 = 0.f;
    #pragma unroll
    for (int i = 0; i < 4; i++) {
        v[i] = x[threadIdx.x + i * 256];
        s += v[i]; s2 += v[i] * v[i];
    }
    s = warpSum(s); s2 = warpSum(s2);
    __shared__ float sh[2][8];
    int w = threadIdx.x >> 5, l = threadIdx.x & 31;
    if (l == 0) { sh[0][w] = s; sh[1][w] = s2; }
    __syncthreads();
    if (w == 0) {
        float a = (l < 8) ? sh[0][l] : 0.f;
        float c = (l < 8) ? sh[1][l] : 0.f;
        a = warpSum(a); c = warpSum(c);
        if (l == 0) { sh[0][0] = a; sh[1][0] = c; }
    }
    __syncthreads();
    float mean = sh[0][0] * (1.0f / DMODEL);
    float var  = sh[1][0] * (1.0f / DMODEL) - mean * mean;
    float rstd = rsqrtf(var + 1e-5f);
    #pragma unroll
    for (int i = 0; i < 4; i++) {
        int c = threadIdx.x + i * 256;
        Y[row * DMODEL + c] = (v[i] - mean) * rstd * g[c] + b[c];
    }
}

// ---------------- row softmax over n=2048, one block per row ----------------
__global__ void __launch_bounds__(256) softmax_kernel(float* __restrict__ S)
{
    long row = blockIdx.x;
    float* p = S + row * (long)SEQ;
    float v[8];
    float mx = -1e30f;
    #pragma unroll
    for (int i = 0; i < 8; i++) { v[i] = p[threadIdx.x + i * 256]; mx = fmaxf(mx, v[i]); }
    mx = warpMax(mx);
    __shared__ float sh[8];
    int w = threadIdx.x >> 5, l = threadIdx.x & 31;
    if (l == 0) sh[w] = mx;
    __syncthreads();
    if (w == 0) {
        float a = (l < 8) ? sh[l] : -1e30f;
        a = warpMax(a);
        if (l == 0) sh[0] = a;
    }
    __syncthreads();
    mx = sh[0];
    __syncthreads();
    float sum = 0.f;
    #pragma unroll
    for (int i = 0; i < 8; i++) { v[i] = expf(v[i] - mx); sum += v[i]; }
    sum = warpSum(sum);
    if (l == 0) sh[w] = sum;
    __syncthreads();
    if (w == 0) {
        float a = (l < 8) ? sh[l] : 0.f;
        a = warpSum(a);
        if (l == 0) sh[0] = a;
    }
    __syncthreads();
    float inv = 1.0f / sh[0];
    #pragma unroll
    for (int i = 0; i < 8; i++) p[threadIdx.x + i * 256] = v[i] * inv;
}

// ---------------- generic TF32 WMMA GEMM ----------------
// C[M,N] = alpha * A[M,K] @ op(B) (+bias)(+gelu)(+residual)
// op(B) = B[K,N] (TB=false, row stride ldb) or Bt[N,K]^T (TB=true, Bt row stride ldb)
// Batch (blockIdx.z): offsets computed as (z/HH)*sH + (z%HH)*sL per operand.
// epi: 0 none, 1 +bias, 2 gelu(x+bias), 3 x+bias+Res
#define BM 128
#define BN 64
#define BK 32
#define LDA_S (BK + 8)   // 40
#define LDB_S (BN + 8)   // 72

template <bool TB>
__global__ void __launch_bounds__(256) gemm_tf32(
    const float* __restrict__ A, const float* __restrict__ B,
    const float* __restrict__ bias, const float* __restrict__ Res,
    float* __restrict__ C,
    int M, int N, int K, int lda, int ldb, int ldc,
    int HH, long saH, long saL, long sbH, long sbL, long scH, long scL,
    float alpha, int epi)
{
    __shared__ float smem[8192];            // 32 KB: load stage (7424) / epilogue (8192)
    float* sA = smem;                       // [BM][LDA_S]
    float* sB = smem + BM * LDA_S;          // [BK][LDB_S]

    int z = blockIdx.z;
    A += (long)(z / HH) * saH + (long)(z % HH) * saL;
    B += (long)(z / HH) * sbH + (long)(z % HH) * sbL;
    C += (long)(z / HH) * scH + (long)(z % HH) * scL;

    const int m0 = blockIdx.y * BM;
    const int n0 = blockIdx.x * BN;
    const int tid = threadIdx.x;
    const int wid = tid >> 5;
    const int wr = wid >> 1;   // 0..3 warp row
    const int wc = wid & 1;    // 0..1 warp col

    wmma::fragment<wmma::accumulator, 16, 16, 8, float> acc[2][2];
    #pragma unroll
    for (int i = 0; i < 2; i++)
        #pragma unroll
        for (int j = 0; j < 2; j++)
            wmma::fill_fragment(acc[i][j], 0.0f);

    for (int k0 = 0; k0 < K; k0 += BK) {
        // load A tile: 128x32 floats = 1024 float4, 4 per thread
        #pragma unroll
        for (int i = 0; i < 4; i++) {
            int f4i = tid + i * 256;
            int row = f4i >> 3, cq = f4i & 7;
            float4 vv = *(const float4*)(A + (long)(m0 + row) * lda + k0 + cq * 4);
            *(float4*)(sA + row * LDA_S + cq * 4) = vv;
        }
        if (!TB) {
            // B tile: 32x64 floats = 512 float4, 2 per thread
            #pragma unroll
            for (int i = 0; i < 2; i++) {
                int f4i = tid + i * 256;
                int row = f4i >> 4, cq = f4i & 15;
                float4 vv = *(const float4*)(B + (long)(k0 + row) * ldb + n0 + cq * 4);
                *(float4*)(sB + row * LDB_S + cq * 4) = vv;
            }
        } else {
            // B logical [k][n] = Bt[n][k]; load float4 along k, scatter-transpose
            #pragma unroll
            for (int i = 0; i < 2; i++) {
                int id = tid + i * 256;        // 0..511
                int n = id >> 3, kq = id & 7;
                float4 vv = *(const float4*)(B + (long)(n0 + n) * ldb + k0 + kq * 4);
                sB[(kq * 4 + 0) * LDB_S + n] = vv.x;
                sB[(kq * 4 + 1) * LDB_S + n] = vv.y;
                sB[(kq * 4 + 2) * LDB_S + n] = vv.z;
                sB[(kq * 4 + 3) * LDB_S + n] = vv.w;
            }
        }
        __syncthreads();

        #pragma unroll
        for (int kk = 0; kk < BK; kk += 8) {
            wmma::fragment<wmma::matrix_a, 16, 16, 8, wmma::precision::tf32, wmma::row_major> af[2];
            wmma::fragment<wmma::matrix_b, 16, 16, 8, wmma::precision::tf32, wmma::row_major> bf[2];
            #pragma unroll
            for (int i = 0; i < 2; i++) {
                wmma::load_matrix_sync(af[i], sA + (wr * 32 + i * 16) * LDA_S + kk, LDA_S);
                #pragma unroll
                for (int t = 0; t < af[i].num_elements; t++)
                    af[i].x[t] = wmma::__float_to_tf32(af[i].x[t]);
            }
            #pragma unroll
            for (int j = 0; j < 2; j++) {
                wmma::load_matrix_sync(bf[j], sB + kk * LDB_S + wc * 32 + j * 16, LDB_S);
                #pragma unroll
                for (int t = 0; t < bf[j].num_elements; t++)
                    bf[j].x[t] = wmma::__float_to_tf32(bf[j].x[t]);
            }
            #pragma unroll
            for (int i = 0; i < 2; i++)
                #pragma unroll
                for (int j = 0; j < 2; j++)
                    wmma::mma_sync(acc[i][j], af[i], bf[j], acc[i][j]);
        }
        __syncthreads();
    }

    // epilogue through smem
    float* sC = smem;  // [BM][BN]
    #pragma unroll
    for (int i = 0; i < 2; i++)
        #pragma unroll
        for (int j = 0; j < 2; j++)
            wmma::store_matrix_sync(sC + (wr * 32 + i * 16) * BN + wc * 32 + j * 16,
                                    acc[i][j], BN, wmma::mem_row_major);
    __syncthreads();

    #pragma unroll
    for (int i = 0; i < 8; i++) {
        int f4i = tid + i * 256;           // 0..2047
        int row = f4i >> 4, cq = f4i & 15;
        float4 vv = *(float4*)(sC + row * BN + cq * 4);
        int gm = m0 + row, gn = n0 + cq * 4;
        float r[4] = {vv.x, vv.y, vv.z, vv.w};
        #pragma unroll
        for (int c2 = 0; c2 < 4; c2++) {
            float val = r[c2] * alpha;
            if (epi >= 1) val += bias[gn + c2];
            if (epi == 2) val = gelu_f(val);
            if (epi == 3) val += Res[(long)gm * ldc + gn + c2];
            r[c2] = val;
        }
        float4 o = make_float4(r[0], r[1], r[2], r[3]);
        *(float4*)(C + (long)gm * ldc + gn) = o;
    }
}

// ---------------- launch ----------------
extern "C" void kernel_launch(void* const* d_in, const int* in_sizes, int n_in,
                              void* d_out, int out_size)
{
    const float* x   = (const float*)d_in[0];
    const float* Wq  = (const float*)d_in[1];
    const float* bq  = (const float*)d_in[2];
    const float* Wk  = (const float*)d_in[3];
    const float* bk  = (const float*)d_in[4];
    const float* Wv  = (const float*)d_in[5];
    const float* bv  = (const float*)d_in[6];
    const float* Wp  = (const float*)d_in[7];
    const float* bp  = (const float*)d_in[8];
    const float* W1  = (const float*)d_in[9];
    const float* b1  = (const float*)d_in[10];
    const float* W2  = (const float*)d_in[11];
    const float* b2  = (const float*)d_in[12];
    const float* g1  = (const float*)d_in[13];
    const float* be1 = (const float*)d_in[14];
    const float* g2  = (const float*)d_in[15];
    const float* be2 = (const float*)d_in[16];
    float* out = (float*)d_out;

    float *h, *q, *k, *v, *sc, *att, *x1, *h2, *ff;
    cudaGetSymbolAddress((void**)&h,   g_h);
    cudaGetSymbolAddress((void**)&q,   g_q);
    cudaGetSymbolAddress((void**)&k,   g_k);
    cudaGetSymbolAddress((void**)&v,   g_v);
    cudaGetSymbolAddress((void**)&sc,  g_sc);
    cudaGetSymbolAddress((void**)&att, g_att);
    cudaGetSymbolAddress((void**)&x1,  g_x1);
    cudaGetSymbolAddress((void**)&h2,  g_h2);
    cudaGetSymbolAddress((void**)&ff,  g_ff);

    const long SD = (long)SEQ * DMODEL;     // per-batch stride in q/k/v/att
    const long SS = (long)SEQ * SEQ;        // per-head score stride

    // 1) LN1
    ln_kernel<<<NTOK, 256>>>(x, g1, be1, h);

    // 2) Q, K, V projections: [4096,1024] @ [1024,1024] + bias
    dim3 gProj(DMODEL / BN, NTOK / BM, 1);
    gemm_tf32<false><<<gProj, 256>>>(h, Wq, bq, nullptr, q,
        NTOK, DMODEL, DMODEL, DMODEL, DMODEL, DMODEL,
        1, 0, 0, 0, 0, 0, 0, 1.0f, 1);
    gemm_tf32<false><<<gProj, 256>>>(h, Wk, bk, nullptr, k,
        NTOK, DMODEL, DMODEL, DMODEL, DMODEL, DMODEL,
        1, 0, 0, 0, 0, 0, 0, 1.0f, 1);
    gemm_tf32<false><<<gProj, 256>>>(h, Wv, bv, nullptr, v,
        NTOK, DMODEL, DMODEL, DMODEL, DMODEL, DMODEL,
        1, 0, 0, 0, 0, 0, 0, 1.0f, 1);

    // 3) scores = Q @ K^T / 8, batched over (b,h) = 32
    dim3 gScores(SEQ / BN, SEQ / BM, NBATCH * NHEADS);
    gemm_tf32<true><<<gScores, 256>>>(q, k, nullptr, nullptr, sc,
        SEQ, SEQ, HEADD, DMODEL, DMODEL, SEQ,
        NHEADS, SD, HEADD, SD, HEADD, (long)NHEADS * SS, SS,
        0.125f, 0);

    // 4) softmax over each of 32*2048 rows
    softmax_kernel<<<NBATCH * NHEADS * SEQ, 256>>>(sc);

    // 5) attn_out = scores @ V  (writes head slices into [T,1024] layout)
    dim3 gAV(HEADD / BN, SEQ / BM, NBATCH * NHEADS);
    gemm_tf32<false><<<gAV, 256>>>(sc, v, nullptr, nullptr, att,
        SEQ, HEADD, SEQ, SEQ, DMODEL, DMODEL,
        NHEADS, (long)NHEADS * SS, SS, SD, HEADD, SD, HEADD,
        1.0f, 0);

    // 6) x1 = x + attn_out @ Wp + bp
    gemm_tf32<false><<<gProj, 256>>>(att, Wp, bp, x, x1,
        NTOK, DMODEL, DMODEL, DMODEL, DMODEL, DMODEL,
        1, 0, 0, 0, 0, 0, 0, 1.0f, 3);

    // 7) LN2
    ln_kernel<<<NTOK, 256>>>(x1, g2, be2, h2);

    // 8) ff = gelu(h2 @ W1 + b1)
    dim3 gFF1(DFF / BN, NTOK / BM, 1);
    gemm_tf32<false><<<gFF1, 256>>>(h2, W1, b1, nullptr, ff,
        NTOK, DFF, DMODEL, DMODEL, DFF, DFF,
        1, 0, 0, 0, 0, 0, 0, 1.0f, 2);

    // 9) out = x1 + ff @ W2 + b2
    dim3 gFF2(DMODEL / BN, NTOK / BM, 1);
    gemm_tf32<false><<<gFF2, 256>>>(ff, W2, b2, x1, out,
        NTOK, DMODEL, DFF, DFF, DMODEL, DMODEL,
        1, 0, 0, 0, 0, 0, 0, 1.0f, 3);
}